// round 8
// baseline (speedup 1.0000x reference)
#include <cuda_runtime.h>
#include <cuda_bf16.h>
#include <math.h>

// Problem constants
#define CLOUDS 64
#define PPC    128      // points per cloud
#define DIM    128
#define NNODES (CLOUDS * PPC)   // 8192
#define EPSV   1e-5f

typedef unsigned long long ull;

// ---------------- scratch (device globals; no allocation allowed) -------------
__device__ float g_Y[NNODES * DIM];     // X @ W1
__device__ float g_P2[NNODES * DIM];    // branch-2 pooled
__device__ float g_ps[128 * 128];       // per-CTA partial sums (batchnorm)
__device__ float g_pss[128 * 128];      // per-CTA partial sums of squares
__device__ float g_bstats[256];         // [0:128) scale, [128:256) shift
__device__ unsigned g_cnt;              // last-block ticket (reset each launch)

// ---------------- f32x2 / approx helpers --------------------------------------
__device__ __forceinline__ ull pack2(float lo, float hi) {
    ull r; asm("mov.b64 %0, {%1, %2};" : "=l"(r) : "f"(lo), "f"(hi)); return r;
}
__device__ __forceinline__ void unpack2(ull v, float& lo, float& hi) {
    asm("mov.b64 {%0, %1}, %2;" : "=f"(lo), "=f"(hi) : "l"(v));
}
__device__ __forceinline__ ull fma2(ull a, ull b, ull c) {
    ull d; asm("fma.rn.f32x2 %0, %1, %2, %3;" : "=l"(d) : "l"(a), "l"(b), "l"(c)); return d;
}
__device__ __forceinline__ ull add2(ull a, ull b) {
    ull d; asm("add.rn.f32x2 %0, %1, %2;" : "=l"(d) : "l"(a), "l"(b)); return d;
}
__device__ __forceinline__ float rsqrt_ap(float x) {
    float r; asm("rsqrt.approx.f32 %0, %1;" : "=f"(r) : "f"(x)); return r;
}
__device__ __forceinline__ float ex2_ap(float x) {
    float r; asm("ex2.approx.f32 %0, %1;" : "=f"(r) : "f"(x)); return r;
}

#define NEG1_2 0xBF800000BF800000ULL  // (-1.0f, -1.0f)
#define LOG2E  1.4426950408889634f

// ============================================================================
// K0: Y = X @ W1  (fp32, f32x2 packed FMAs). 128 CTAs x 512 threads,
// each CTA computes 64 rows. Thread = (rowblk 0..7) x (colpair 0..63):
// 8 rows x 2 cols per thread -> acc is only 8 ull, ~60 regs, 16 warps/SM.
// ============================================================================
__global__ void __launch_bounds__(512, 1)
k0_gemm(const float* __restrict__ X, const float* __restrict__ W1) {
    extern __shared__ ull sm0[];
    ull* wp = sm0;            // [128 k][64 col-pairs]  (64 KB)
    ull* xd = sm0 + 8192;     // [128 k][64 rows] duplicated (v,v)  (64 KB)

    const int tid = threadIdx.x;
    const int r0  = blockIdx.x * 64;

    // copy W1 (64 KB) into smem
    const float4* w4 = (const float4*)W1;
    float4* wps = (float4*)wp;
    #pragma unroll
    for (int t = 0; t < 8; t++) wps[tid + t * 512] = w4[tid + t * 512];

    // transpose + duplicate X block: xd[k*64 + r] = (x, x)
    #pragma unroll
    for (int t = 0; t < 16; t++) {
        int idx = tid + t * 512;
        int r = idx & 63;
        int k = idx >> 6;
        float v = X[(r0 + r) * DIM + k];
        xd[k * 64 + r] = pack2(v, v);
    }
    __syncthreads();

    const int rb = tid >> 6;   // 8 row-blocks of 8 rows (warp-uniform -> bcast LDS)
    const int cp = tid & 63;   // 64 col-pairs

    ull acc[8];
    #pragma unroll
    for (int r = 0; r < 8; r++) acc[r] = 0ULL;

    #pragma unroll 4
    for (int k = 0; k < 128; k++) {
        const ulonglong2* xv = (const ulonglong2*)(xd + k * 64 + rb * 8);
        ulonglong2 x0 = xv[0], x1 = xv[1], x2 = xv[2], x3 = xv[3];
        ull xr[8] = {x0.x, x0.y, x1.x, x1.y, x2.x, x2.y, x3.x, x3.y};
        ull wv = wp[k * 64 + cp];
        #pragma unroll
        for (int r = 0; r < 8; r++) acc[r] = fma2(xr[r], wv, acc[r]);
    }

    #pragma unroll
    for (int r = 0; r < 8; r++) {
        int row = r0 + rb * 8 + r;
        ((ull*)(g_Y + row * DIM))[cp] = acc[r];
    }
}

// ============================================================================
// K2: branch 2.  p2[i,d] = sum_j relu(z_i[d]-z_j[d]),  z = xyz @ W_xyz.
// Writes g_P2 + per-CTA batchnorm partials; LAST CTA reduces partials into
// g_bstats (scale/shift) deterministically.
// ============================================================================
#define ST_STRIDE 132
__global__ void __launch_bounds__(512, 1)
k2_branch2(const float* __restrict__ XYZ, const float* __restrict__ Wxyz,
           const float* __restrict__ bn_g, const float* __restrict__ bn_b) {
    extern __shared__ float sm2[];
    float* zs   = sm2;                       // [128][128]       (16384 f)
    float* st   = sm2 + 16384;               // [64][132] stage  (8448 f)
    float* xyzs = sm2 + 16384 + 8448;        // [128][4]         (512 f)
    float* wxs  = xyzs + 512;                // [3][128]         (384 f)

    const int tid  = threadIdx.x;
    const int w    = tid >> 5;
    const int lane = tid & 31;
    const int i_l   = ((w & 1) << 5) | lane;
    const int dbase = (w >> 1) << 4;

    const int cta   = blockIdx.x;
    const int node0 = (cta >> 1) << 7;
    const int i0    = (cta & 1) << 6;

    if (tid < 128) {
        const float* p = XYZ + (node0 + tid) * 3;
        xyzs[tid * 4 + 0] = p[0];
        xyzs[tid * 4 + 1] = p[1];
        xyzs[tid * 4 + 2] = p[2];
        xyzs[tid * 4 + 3] = 0.f;
    }
    if (tid < 384) wxs[tid] = Wxyz[tid];
    __syncthreads();

    // z for the whole cloud
    #pragma unroll
    for (int t = 0; t < 32; t++) {
        int idx = tid + t * 512;
        int jn = idx >> 7;
        int d  = idx & 127;
        zs[idx] = xyzs[(jn << 2) + 0] * wxs[d]
                + xyzs[(jn << 2) + 1] * wxs[128 + d]
                + xyzs[(jn << 2) + 2] * wxs[256 + d];
    }
    __syncthreads();

    ull zi[8];
    {
        const ull* zsu = (const ull*)zs;
        int zoff = (((i0 + i_l) << 7) + dbase) >> 1;
        #pragma unroll
        for (int p = 0; p < 8; p++) zi[p] = zsu[zoff + p];
    }
    ull acc[8];
    #pragma unroll
    for (int p = 0; p < 8; p++) acc[p] = 0ULL;

    #pragma unroll 4
    for (int j = 0; j < 128; j++) {
        const ulonglong2* zj2 = (const ulonglong2*)(zs + (j << 7) + dbase);
        ulonglong2 a0 = zj2[0], a1 = zj2[1], a2 = zj2[2], a3 = zj2[3];
        ull zj[8] = {a0.x, a0.y, a1.x, a1.y, a2.x, a2.y, a3.x, a3.y};
        #pragma unroll
        for (int p = 0; p < 8; p++) {
            ull df = fma2(zj[p], NEG1_2, zi[p]);      // z_i - z_j
            float lo, hi;
            unpack2(df, lo, hi);
            lo = fmaxf(lo, 0.f);
            hi = fmaxf(hi, 0.f);
            acc[p] = add2(acc[p], pack2(lo, hi));
        }
    }

    float af[16];
    #pragma unroll
    for (int p = 0; p < 8; p++) unpack2(acc[p], af[2 * p], af[2 * p + 1]);
    #pragma unroll
    for (int q = 0; q < 4; q++) {
        float4 o;
        o.x = af[q * 4 + 0]; o.y = af[q * 4 + 1];
        o.z = af[q * 4 + 2]; o.w = af[q * 4 + 3];
        *(float4*)(st + i_l * ST_STRIDE + dbase + q * 4) = o;
    }
    __syncthreads();

    if (tid < 128) {
        float S = 0.f, SS = 0.f;
        #pragma unroll 8
        for (int i = 0; i < 64; i++) {
            float v = st[i * ST_STRIDE + tid];
            S += v; SS += v * v;
        }
        g_ps[cta * 128 + tid]  = S;
        g_pss[cta * 128 + tid] = SS;
    }
    const int nb = node0 + i0;
    #pragma unroll
    for (int t = 0; t < 16; t++) {
        int idx = tid + t * 512;     // 0 .. 8191
        int i = idx >> 7;
        int d = idx & 127;
        g_P2[((nb + i) << 7) + d] = st[i * ST_STRIDE + d];
    }

    // ---- last-block: reduce partials -> g_bstats (deterministic fixed order) ----
    __shared__ unsigned s_tk;
    __threadfence();
    if (tid == 0) s_tk = atomicAdd(&g_cnt, 1u);
    __syncthreads();
    if (s_tk == 127u) {
        __threadfence();
        const int d   = tid & 127;
        const int grp = tid >> 7;       // 0..3, 32 CTAs each
        const float* ps  = g_ps  + grp * 32 * 128 + d;
        const float* pss = g_pss + grp * 32 * 128 + d;
        float S = 0.f, SS = 0.f;
        #pragma unroll 8
        for (int c = 0; c < 32; c++) {
            S  += ps[c * 128];
            SS += pss[c * 128];
        }
        st[grp * 128 + d]       = S;     // reuse st
        st[512 + grp * 128 + d] = SS;
        __syncthreads();
        if (tid < 128) {
            float St  = st[tid] + st[128 + tid] + st[256 + tid] + st[384 + tid];
            float SSt = st[512 + tid] + st[640 + tid] + st[768 + tid] + st[896 + tid];
            float mu  = St * (1.f / (float)NNODES);
            float var = SSt * (1.f / (float)NNODES) - mu * mu;
            float inv = 1.f / sqrtf(var + EPSV);
            float scale = inv * bn_g[tid];
            g_bstats[tid]       = scale;
            g_bstats[128 + tid] = bn_b[tid] - mu * scale;
        }
        __threadfence();
        if (tid == 0) g_cnt = 0u;       // reset for next launch
    }
}

// ============================================================================
// K1: branch 1 + fused output.
//   p1[i,d] = sum_j relu(w_ij*(y_i[d]-y_j[d]) + b1[d]) - relu(b1[d])
//   out = x + LN(p1)*ln_g + ln_b + p2*bn_scale + bn_shift
// Grid: 128 CTAs (2 per cloud, 64 nodes each) x 512 threads.
// ============================================================================
__global__ void __launch_bounds__(512, 1)
k1_branch1(const float* __restrict__ X, const float* __restrict__ XYZ,
           const float* __restrict__ b1, const float* __restrict__ ln_g,
           const float* __restrict__ ln_b, float* __restrict__ out) {
    extern __shared__ float sm1[];
    float* ys    = sm1;            // [128][128] Y of the cloud     (16384 f)
    float* ws    = sm1 + 16384;    // [128 j][64 i] edge weights     (8192 f) (reused as red[])
    float* xyzs  = sm1 + 24576;    // [128][4] xyz of the cloud      (512 f)
    float* stats = sm1 + 25088;    // [64] mu + [64] inv             (128 f)

    const int tid  = threadIdx.x;
    const int w    = tid >> 5;
    const int lane = tid & 31;
    const int i_l   = ((w & 1) << 5) | lane;  // 0..63
    const int dbase = (w >> 1) << 4;          // 0..112 step 16

    const int cta   = blockIdx.x;
    const int node0 = (cta >> 1) << 7;   // cloud * 128
    const int i0    = (cta & 1) << 6;    // 0 or 64

    // load cloud Y
    {
        const float4* Yv = (const float4*)(g_Y + node0 * DIM);
        float4* ysv = (float4*)ys;
        #pragma unroll
        for (int t = 0; t < 8; t++) ysv[tid + t * 512] = Yv[tid + t * 512];
    }
    if (tid < 128) {
        const float* p = XYZ + (node0 + tid) * 3;
        xyzs[tid * 4 + 0] = p[0];
        xyzs[tid * 4 + 1] = p[1];
        xyzs[tid * 4 + 2] = p[2];
        xyzs[tid * 4 + 3] = 0.f;
    }
    __syncthreads();

    // precompute w matrix: ws[j*64 + i] = exp(-dist(i0+i, j)); diag -> w=1
    #pragma unroll
    for (int t = 0; t < 16; t++) {
        int idx = tid + t * 512;
        int ii = idx & 63;
        int jj = idx >> 6;
        float dx = xyzs[((i0 + ii) << 2) + 0] - xyzs[(jj << 2) + 0];
        float dy = xyzs[((i0 + ii) << 2) + 1] - xyzs[(jj << 2) + 1];
        float dz = xyzs[((i0 + ii) << 2) + 2] - xyzs[(jj << 2) + 2];
        float d2 = dx * dx + dy * dy + dz * dz;
        float dist = d2 * rsqrt_ap(fmaxf(d2, 1e-30f));   // sqrt(d2)
        ws[(jj << 6) + ii] = ex2_ap(-dist * LOG2E);      // exp(-dist)
    }

    // cache y_i and b1 as packed pairs
    ull yi[8], b1p[8];
    {
        const ull* ysu = (const ull*)ys;
        int yoff = (((i0 + i_l) << 7) + dbase) >> 1;
        const ull* b1u = (const ull*)b1;
        int boff = dbase >> 1;
        #pragma unroll
        for (int p = 0; p < 8; p++) { yi[p] = ysu[yoff + p]; b1p[p] = b1u[boff + p]; }
    }
    ull acc[8];
    #pragma unroll
    for (int p = 0; p < 8; p++) acc[p] = 0ULL;
    __syncthreads();

    // ---- main pairwise loop over j ----
    #pragma unroll 4
    for (int j = 0; j < 128; j++) {
        float wv = ws[(j << 6) + i_l];
        ull w2 = pack2(wv, wv);
        const ulonglong2* yj2 = (const ulonglong2*)(ys + (j << 7) + dbase);
        ulonglong2 a0 = yj2[0], a1 = yj2[1], a2 = yj2[2], a3 = yj2[3];
        ull yj[8] = {a0.x, a0.y, a1.x, a1.y, a2.x, a2.y, a3.x, a3.y};
        #pragma unroll
        for (int p = 0; p < 8; p++) {
            ull df = fma2(yj[p], NEG1_2, yi[p]);      // y_i - y_j
            ull t  = fma2(w2, df, b1p[p]);            // w*diff + b1
            float lo, hi;
            unpack2(t, lo, hi);
            lo = fmaxf(lo, 0.f);
            hi = fmaxf(hi, 0.f);
            acc[p] = add2(acc[p], pack2(lo, hi));
        }
    }

    // ---- epilogue: self-edge correction + per-node LayerNorm + fused BN ----
    float af[16];
    #pragma unroll
    for (int p = 0; p < 8; p++) {
        float lo, hi; unpack2(acc[p], lo, hi);
        float bl, bh; unpack2(b1p[p], bl, bh);
        af[2 * p + 0] = lo - fmaxf(bl, 0.f);     // remove j==i term relu(b1)
        af[2 * p + 1] = hi - fmaxf(bh, 0.f);
    }
    float s = 0.f, ssq = 0.f;
    #pragma unroll
    for (int k = 0; k < 16; k++) { s += af[k]; ssq += af[k] * af[k]; }

    __syncthreads();                 // done reading ws/ys in main loop
    float* red = ws;                 // reuse: red[i][16] partials
    red[i_l * 16 + ((w >> 1) << 1) + 0] = s;
    red[i_l * 16 + ((w >> 1) << 1) + 1] = ssq;
    __syncthreads();

    if (tid < 64) {
        float S = 0.f, SS = 0.f;
        #pragma unroll
        for (int cc = 0; cc < 8; cc++) {
            S  += red[tid * 16 + 2 * cc + 0];
            SS += red[tid * 16 + 2 * cc + 1];
        }
        float mu  = S * (1.f / 128.f);
        float var = SS * (1.f / 128.f) - mu * mu;
        stats[tid]      = mu;
        stats[64 + tid] = 1.f / sqrtf(var + EPSV);
    }
    __syncthreads();

    float mu  = stats[i_l];
    float inv = stats[64 + i_l];
    int gb = ((node0 + i0 + i_l) << 7) + dbase;
    #pragma unroll
    for (int q = 0; q < 4; q++) {
        float4 xv = *(const float4*)(X + gb + q * 4);
        float4 gv = *(const float4*)(ln_g + dbase + q * 4);
        float4 bv = *(const float4*)(ln_b + dbase + q * 4);
        float4 pv = *(const float4*)(g_P2 + gb + q * 4);
        float4 sc = *(const float4*)(g_bstats + dbase + q * 4);
        float4 sh = *(const float4*)(g_bstats + 128 + dbase + q * 4);
        float4 o;
        o.x = xv.x + (af[q * 4 + 0] - mu) * inv * gv.x + bv.x + pv.x * sc.x + sh.x;
        o.y = xv.y + (af[q * 4 + 1] - mu) * inv * gv.y + bv.y + pv.y * sc.y + sh.y;
        o.z = xv.z + (af[q * 4 + 2] - mu) * inv * gv.z + bv.z + pv.z * sc.z + sh.z;
        o.w = xv.w + (af[q * 4 + 3] - mu) * inv * gv.w + bv.w + pv.w * sc.w + sh.w;
        *(float4*)(out + gb + q * 4) = o;
    }
}

// ============================================================================
extern "C" void kernel_launch(void* const* d_in, const int* in_sizes, int n_in,
                              void* d_out, int out_size) {
    const float* X    = (const float*)d_in[0];
    const float* XYZ  = (const float*)d_in[1];
    const float* Wxyz = (const float*)d_in[2];
    const float* bn_g = (const float*)d_in[3];
    const float* bn_b = (const float*)d_in[4];
    const float* W1   = (const float*)d_in[5];
    const float* b1   = (const float*)d_in[6];
    const float* ln_g = (const float*)d_in[7];
    const float* ln_b = (const float*)d_in[8];
    float* out = (float*)d_out;

    const int smem0 = 16384 * 8;                               // 128 KB
    const int smem1 = (16384 + 8192 + 512 + 128) * 4;          // ~100.9 KB
    const int smem2 = (16384 + 8448 + 512 + 384) * 4;          // ~102.9 KB

    cudaFuncSetAttribute(k0_gemm,    cudaFuncAttributeMaxDynamicSharedMemorySize, smem0);
    cudaFuncSetAttribute(k1_branch1, cudaFuncAttributeMaxDynamicSharedMemorySize, smem1);
    cudaFuncSetAttribute(k2_branch2, cudaFuncAttributeMaxDynamicSharedMemorySize, smem2);

    k0_gemm   <<<128, 512, smem0>>>(X, W1);
    k2_branch2<<<128, 512, smem2>>>(XYZ, Wxyz, bn_g, bn_b);
    k1_branch1<<<128, 512, smem1>>>(X, XYZ, b1, ln_g, ln_b, out);
}

// round 9
// speedup vs baseline: 1.0320x; 1.0320x over previous
#include <cuda_runtime.h>
#include <cuda_bf16.h>
#include <math.h>

// Problem constants
#define CLOUDS 64
#define PPC    128      // points per cloud
#define DIM    128
#define NNODES (CLOUDS * PPC)   // 8192
#define EPSV   1e-5f

typedef unsigned long long ull;

// ---------------- scratch (device globals; no allocation allowed) -------------
__device__ float g_Ya[NNODES * DIM];    // X @ W1 (k-half 0)
__device__ float g_Yb[NNODES * DIM];    // X @ W1 (k-half 1)
__device__ float g_P2[NNODES * DIM];    // branch-2 pooled
__device__ float g_ps[128 * 128];       // per-CTA partial sums (batchnorm)
__device__ float g_pss[128 * 128];      // per-CTA partial sums of squares
__device__ float g_bstats[256];         // [0:128) scale, [128:256) shift
__device__ unsigned g_cnt;              // last-block ticket (reset each launch)

// ---------------- f32x2 / approx helpers --------------------------------------
__device__ __forceinline__ ull pack2(float lo, float hi) {
    ull r; asm("mov.b64 %0, {%1, %2};" : "=l"(r) : "f"(lo), "f"(hi)); return r;
}
__device__ __forceinline__ void unpack2(ull v, float& lo, float& hi) {
    asm("mov.b64 {%0, %1}, %2;" : "=f"(lo), "=f"(hi) : "l"(v));
}
__device__ __forceinline__ ull fma2(ull a, ull b, ull c) {
    ull d; asm("fma.rn.f32x2 %0, %1, %2, %3;" : "=l"(d) : "l"(a), "l"(b), "l"(c)); return d;
}
__device__ __forceinline__ ull add2(ull a, ull b) {
    ull d; asm("add.rn.f32x2 %0, %1, %2;" : "=l"(d) : "l"(a), "l"(b)); return d;
}
__device__ __forceinline__ float rsqrt_ap(float x) {
    float r; asm("rsqrt.approx.f32 %0, %1;" : "=f"(r) : "f"(x)); return r;
}
__device__ __forceinline__ float ex2_ap(float x) {
    float r; asm("ex2.approx.f32 %0, %1;" : "=f"(r) : "f"(x)); return r;
}

#define NEG1_2 0xBF800000BF800000ULL  // (-1.0f, -1.0f)
#define LOG2E  1.4426950408889634f

// ============================================================================
// K0: Y = X @ W1, K-SPLIT: grid 256 = 128 row-blocks x 2 k-halves.
// Each CTA: 64 rows x 128 cols x 64 k, 64 KB smem -> 2 CTAs/SM (16 warps).
// k-half 0 writes g_Ya, k-half 1 writes g_Yb; k1 sums them on load.
// Inner mapping = wavefront-minimal R6 shape: 8 warps, thread = 8 rows x 2 cp.
// ============================================================================
__global__ void __launch_bounds__(256, 2)
k0_gemm(const float* __restrict__ X, const float* __restrict__ W1) {
    extern __shared__ ull sm0[];
    ull* wp = sm0;            // [64 k][64 col-pairs]  (32 KB)
    ull* xd = sm0 + 4096;     // [64 k][64 rows] duplicated (v,v)  (32 KB)

    const int tid = threadIdx.x;
    const int r0  = (blockIdx.x >> 1) * 64;
    const int kb  = (blockIdx.x & 1) * 64;

    // copy W1 rows [kb, kb+64) (32 KB) into smem
    const float4* w4 = (const float4*)W1 + kb * 32;
    float4* wps = (float4*)wp;
    #pragma unroll
    for (int t = 0; t < 8; t++) wps[tid + t * 256] = w4[tid + t * 256];

    // transpose + duplicate X block: xd[k*64 + r] = (x, x)
    #pragma unroll
    for (int t = 0; t < 16; t++) {
        int idx = tid + t * 256;      // 0..4095
        int r = idx & 63;
        int k = idx >> 6;
        float v = X[(r0 + r) * DIM + kb + k];
        xd[k * 64 + r] = pack2(v, v);
    }
    __syncthreads();

    const int rb = tid >> 5;   // 8 row-blocks of 8 rows (warp-uniform -> bcast LDS)
    const int cb = tid & 31;   // 32 col-blocks of 4 cols (2 pairs)

    ull acc[8][2];
    #pragma unroll
    for (int r = 0; r < 8; r++) { acc[r][0] = 0ULL; acc[r][1] = 0ULL; }

    #pragma unroll 2
    for (int k = 0; k < 64; k++) {
        const ulonglong2* xv = (const ulonglong2*)(xd + k * 64 + rb * 8);
        ulonglong2 x0 = xv[0], x1 = xv[1], x2 = xv[2], x3 = xv[3];
        ull xr[8] = {x0.x, x0.y, x1.x, x1.y, x2.x, x2.y, x3.x, x3.y};
        ulonglong2 wv = *(const ulonglong2*)(wp + k * 64 + cb * 2);
        #pragma unroll
        for (int r = 0; r < 8; r++) {
            acc[r][0] = fma2(xr[r], wv.x, acc[r][0]);
            acc[r][1] = fma2(xr[r], wv.y, acc[r][1]);
        }
    }

    float* dst = (blockIdx.x & 1) ? g_Yb : g_Ya;
    #pragma unroll
    for (int r = 0; r < 8; r++) {
        int row = r0 + rb * 8 + r;
        float a, b, c, d;
        unpack2(acc[r][0], a, b);
        unpack2(acc[r][1], c, d);
        float4 o; o.x = a; o.y = b; o.z = c; o.w = d;
        ((float4*)(dst + row * DIM))[cb] = o;
    }
}

// ============================================================================
// K2: branch 2.  p2[i,d] = sum_j relu(z_i[d]-z_j[d]),  z = xyz @ W_xyz.
// Writes g_P2 + per-CTA batchnorm partials; LAST CTA reduces partials into
// g_bstats (scale/shift) deterministically.
// ============================================================================
#define ST_STRIDE 132
__global__ void __launch_bounds__(512, 1)
k2_branch2(const float* __restrict__ XYZ, const float* __restrict__ Wxyz,
           const float* __restrict__ bn_g, const float* __restrict__ bn_b) {
    extern __shared__ float sm2[];
    float* zs   = sm2;                       // [128][128]       (16384 f)
    float* st   = sm2 + 16384;               // [64][132] stage  (8448 f)
    float* xyzs = sm2 + 16384 + 8448;        // [128][4]         (512 f)
    float* wxs  = xyzs + 512;                // [3][128]         (384 f)

    const int tid  = threadIdx.x;
    const int w    = tid >> 5;
    const int lane = tid & 31;
    const int i_l   = ((w & 1) << 5) | lane;
    const int dbase = (w >> 1) << 4;

    const int cta   = blockIdx.x;
    const int node0 = (cta >> 1) << 7;
    const int i0    = (cta & 1) << 6;

    if (tid < 128) {
        const float* p = XYZ + (node0 + tid) * 3;
        xyzs[tid * 4 + 0] = p[0];
        xyzs[tid * 4 + 1] = p[1];
        xyzs[tid * 4 + 2] = p[2];
        xyzs[tid * 4 + 3] = 0.f;
    }
    if (tid < 384) wxs[tid] = Wxyz[tid];
    __syncthreads();

    // z for the whole cloud
    #pragma unroll
    for (int t = 0; t < 32; t++) {
        int idx = tid + t * 512;
        int jn = idx >> 7;
        int d  = idx & 127;
        zs[idx] = xyzs[(jn << 2) + 0] * wxs[d]
                + xyzs[(jn << 2) + 1] * wxs[128 + d]
                + xyzs[(jn << 2) + 2] * wxs[256 + d];
    }
    __syncthreads();

    ull zi[8];
    {
        const ull* zsu = (const ull*)zs;
        int zoff = (((i0 + i_l) << 7) + dbase) >> 1;
        #pragma unroll
        for (int p = 0; p < 8; p++) zi[p] = zsu[zoff + p];
    }
    ull acc[8];
    #pragma unroll
    for (int p = 0; p < 8; p++) acc[p] = 0ULL;

    #pragma unroll 4
    for (int j = 0; j < 128; j++) {
        const ulonglong2* zj2 = (const ulonglong2*)(zs + (j << 7) + dbase);
        ulonglong2 a0 = zj2[0], a1 = zj2[1], a2 = zj2[2], a3 = zj2[3];
        ull zj[8] = {a0.x, a0.y, a1.x, a1.y, a2.x, a2.y, a3.x, a3.y};
        #pragma unroll
        for (int p = 0; p < 8; p++) {
            ull df = fma2(zj[p], NEG1_2, zi[p]);      // z_i - z_j
            float lo, hi;
            unpack2(df, lo, hi);
            lo = fmaxf(lo, 0.f);
            hi = fmaxf(hi, 0.f);
            acc[p] = add2(acc[p], pack2(lo, hi));
        }
    }

    float af[16];
    #pragma unroll
    for (int p = 0; p < 8; p++) unpack2(acc[p], af[2 * p], af[2 * p + 1]);
    #pragma unroll
    for (int q = 0; q < 4; q++) {
        float4 o;
        o.x = af[q * 4 + 0]; o.y = af[q * 4 + 1];
        o.z = af[q * 4 + 2]; o.w = af[q * 4 + 3];
        *(float4*)(st + i_l * ST_STRIDE + dbase + q * 4) = o;
    }
    __syncthreads();

    if (tid < 128) {
        float S = 0.f, SS = 0.f;
        #pragma unroll 8
        for (int i = 0; i < 64; i++) {
            float v = st[i * ST_STRIDE + tid];
            S += v; SS += v * v;
        }
        g_ps[cta * 128 + tid]  = S;
        g_pss[cta * 128 + tid] = SS;
    }
    const int nb = node0 + i0;
    #pragma unroll
    for (int t = 0; t < 16; t++) {
        int idx = tid + t * 512;     // 0 .. 8191
        int i = idx >> 7;
        int d = idx & 127;
        g_P2[((nb + i) << 7) + d] = st[i * ST_STRIDE + d];
    }

    // ---- last-block: reduce partials -> g_bstats (deterministic fixed order) ----
    __shared__ unsigned s_tk;
    __threadfence();
    if (tid == 0) s_tk = atomicAdd(&g_cnt, 1u);
    __syncthreads();
    if (s_tk == 127u) {
        __threadfence();
        const int d   = tid & 127;
        const int grp = tid >> 7;       // 0..3, 32 CTAs each
        const float* ps  = g_ps  + grp * 32 * 128 + d;
        const float* pss = g_pss + grp * 32 * 128 + d;
        float S = 0.f, SS = 0.f;
        #pragma unroll 8
        for (int c = 0; c < 32; c++) {
            S  += ps[c * 128];
            SS += pss[c * 128];
        }
        st[grp * 128 + d]       = S;     // reuse st
        st[512 + grp * 128 + d] = SS;
        __syncthreads();
        if (tid < 128) {
            float St  = st[tid] + st[128 + tid] + st[256 + tid] + st[384 + tid];
            float SSt = st[512 + tid] + st[640 + tid] + st[768 + tid] + st[896 + tid];
            float mu  = St * (1.f / (float)NNODES);
            float var = SSt * (1.f / (float)NNODES) - mu * mu;
            float inv = 1.f / sqrtf(var + EPSV);
            float scale = inv * bn_g[tid];
            g_bstats[tid]       = scale;
            g_bstats[128 + tid] = bn_b[tid] - mu * scale;
        }
        __threadfence();
        if (tid == 0) g_cnt = 0u;       // reset for next launch
    }
}

// ============================================================================
// K1: branch 1 + fused output.  1024 threads: 64 i x 16 d-chunks (8 floats).
//   p1[i,d] = sum_j relu(w_ij*(y_i[d]-y_j[d]) + b1[d]) - relu(b1[d])
//   out = x + LN(p1)*ln_g + ln_b + p2*bn_scale + bn_shift
// Grid: 128 CTAs (2 per cloud, 64 nodes each).
// ============================================================================
__global__ void __launch_bounds__(1024, 1)
k1_branch1(const float* __restrict__ X, const float* __restrict__ XYZ,
           const float* __restrict__ b1, const float* __restrict__ ln_g,
           const float* __restrict__ ln_b, float* __restrict__ out) {
    extern __shared__ float sm1[];
    float* ys    = sm1;            // [128][128] Y of the cloud     (16384 f)
    float* ws    = sm1 + 16384;    // [128 j][64 i] edge weights     (8192 f) (reused as red[])
    float* xyzs  = sm1 + 24576;    // [128][4] xyz of the cloud      (512 f)
    float* stats = sm1 + 25088;    // [64] mu + [64] inv             (128 f)

    const int tid  = threadIdx.x;
    const int w    = tid >> 5;                 // 0..31
    const int lane = tid & 31;
    const int i_l    = ((w & 1) << 5) | lane;  // 0..63
    const int dchunk = w >> 1;                 // 0..15
    const int dbase  = dchunk << 3;            // 0..120 step 8

    const int cta   = blockIdx.x;
    const int node0 = (cta >> 1) << 7;   // cloud * 128
    const int i0    = (cta & 1) << 6;    // 0 or 64

    // load cloud Y = g_Ya + g_Yb
    {
        const float4* Ya = (const float4*)(g_Ya + node0 * DIM);
        const float4* Yb = (const float4*)(g_Yb + node0 * DIM);
        float4* ysv = (float4*)ys;
        #pragma unroll
        for (int t = 0; t < 4; t++) {
            int idx = tid + t * 1024;
            float4 a = Ya[idx], b = Yb[idx];
            float4 o; o.x = a.x + b.x; o.y = a.y + b.y; o.z = a.z + b.z; o.w = a.w + b.w;
            ysv[idx] = o;
        }
    }
    if (tid < 128) {
        const float* p = XYZ + (node0 + tid) * 3;
        xyzs[tid * 4 + 0] = p[0];
        xyzs[tid * 4 + 1] = p[1];
        xyzs[tid * 4 + 2] = p[2];
        xyzs[tid * 4 + 3] = 0.f;
    }
    __syncthreads();

    // precompute w matrix: ws[j*64 + i] = exp(-dist(i0+i, j)); diag -> w=1
    #pragma unroll
    for (int t = 0; t < 8; t++) {
        int idx = tid + t * 1024;
        int ii = idx & 63;
        int jj = idx >> 6;
        float dx = xyzs[((i0 + ii) << 2) + 0] - xyzs[(jj << 2) + 0];
        float dy = xyzs[((i0 + ii) << 2) + 1] - xyzs[(jj << 2) + 1];
        float dz = xyzs[((i0 + ii) << 2) + 2] - xyzs[(jj << 2) + 2];
        float d2 = dx * dx + dy * dy + dz * dz;
        float dist = d2 * rsqrt_ap(fmaxf(d2, 1e-30f));   // sqrt(d2)
        ws[(jj << 6) + ii] = ex2_ap(-dist * LOG2E);      // exp(-dist)
    }

    // cache y_i and b1 as packed pairs (4 ull = 8 floats each)
    ull yi[4], b1p[4];
    {
        const ull* ysu = (const ull*)ys;
        int yoff = (((i0 + i_l) << 7) + dbase) >> 1;
        const ull* b1u = (const ull*)b1;
        int boff = dbase >> 1;
        #pragma unroll
        for (int p = 0; p < 4; p++) { yi[p] = ysu[yoff + p]; b1p[p] = b1u[boff + p]; }
    }
    ull acc[4];
    #pragma unroll
    for (int p = 0; p < 4; p++) acc[p] = 0ULL;
    __syncthreads();

    // ---- main pairwise loop over j ----
    #pragma unroll 4
    for (int j = 0; j < 128; j++) {
        float wv = ws[(j << 6) + i_l];
        ull w2 = pack2(wv, wv);
        const ulonglong2* yj2 = (const ulonglong2*)(ys + (j << 7) + dbase);
        ulonglong2 a0 = yj2[0], a1 = yj2[1];
        ull yj[4] = {a0.x, a0.y, a1.x, a1.y};
        #pragma unroll
        for (int p = 0; p < 4; p++) {
            ull df = fma2(yj[p], NEG1_2, yi[p]);      // y_i - y_j
            ull t  = fma2(w2, df, b1p[p]);            // w*diff + b1
            float lo, hi;
            unpack2(t, lo, hi);
            lo = fmaxf(lo, 0.f);
            hi = fmaxf(hi, 0.f);
            acc[p] = add2(acc[p], pack2(lo, hi));
        }
    }

    // ---- epilogue: self-edge correction + per-node LayerNorm + fused BN ----
    float af[8];
    #pragma unroll
    for (int p = 0; p < 4; p++) {
        float lo, hi; unpack2(acc[p], lo, hi);
        float bl, bh; unpack2(b1p[p], bl, bh);
        af[2 * p + 0] = lo - fmaxf(bl, 0.f);     // remove j==i term relu(b1)
        af[2 * p + 1] = hi - fmaxf(bh, 0.f);
    }
    float s = 0.f, ssq = 0.f;
    #pragma unroll
    for (int k = 0; k < 8; k++) { s += af[k]; ssq += af[k] * af[k]; }

    __syncthreads();                 // done reading ws/ys in main loop
    float* red = ws;                 // reuse: red[i][32] partials
    red[i_l * 32 + dchunk * 2 + 0] = s;
    red[i_l * 32 + dchunk * 2 + 1] = ssq;
    __syncthreads();

    if (tid < 64) {
        float S = 0.f, SS = 0.f;
        #pragma unroll
        for (int cc = 0; cc < 16; cc++) {
            S  += red[tid * 32 + 2 * cc + 0];
            SS += red[tid * 32 + 2 * cc + 1];
        }
        float mu  = S * (1.f / 128.f);
        float var = SS * (1.f / 128.f) - mu * mu;
        stats[tid]      = mu;
        stats[64 + tid] = 1.f / sqrtf(var + EPSV);
    }
    __syncthreads();

    float mu  = stats[i_l];
    float inv = stats[64 + i_l];
    int gb = ((node0 + i0 + i_l) << 7) + dbase;
    #pragma unroll
    for (int q = 0; q < 2; q++) {
        float4 xv = *(const float4*)(X + gb + q * 4);
        float4 gv = *(const float4*)(ln_g + dbase + q * 4);
        float4 bv = *(const float4*)(ln_b + dbase + q * 4);
        float4 pv = *(const float4*)(g_P2 + gb + q * 4);
        float4 sc = *(const float4*)(g_bstats + dbase + q * 4);
        float4 sh = *(const float4*)(g_bstats + 128 + dbase + q * 4);
        float4 o;
        o.x = xv.x + (af[q * 4 + 0] - mu) * inv * gv.x + bv.x + pv.x * sc.x + sh.x;
        o.y = xv.y + (af[q * 4 + 1] - mu) * inv * gv.y + bv.y + pv.y * sc.y + sh.y;
        o.z = xv.z + (af[q * 4 + 2] - mu) * inv * gv.z + bv.z + pv.z * sc.z + sh.z;
        o.w = xv.w + (af[q * 4 + 3] - mu) * inv * gv.w + bv.w + pv.w * sc.w + sh.w;
        *(float4*)(out + gb + q * 4) = o;
    }
}

// ============================================================================
extern "C" void kernel_launch(void* const* d_in, const int* in_sizes, int n_in,
                              void* d_out, int out_size) {
    const float* X    = (const float*)d_in[0];
    const float* XYZ  = (const float*)d_in[1];
    const float* Wxyz = (const float*)d_in[2];
    const float* bn_g = (const float*)d_in[3];
    const float* bn_b = (const float*)d_in[4];
    const float* W1   = (const float*)d_in[5];
    const float* b1   = (const float*)d_in[6];
    const float* ln_g = (const float*)d_in[7];
    const float* ln_b = (const float*)d_in[8];
    float* out = (float*)d_out;

    const int smem0 = 8192 * 8;                                // 64 KB
    const int smem1 = (16384 + 8192 + 512 + 128) * 4;          // ~100.9 KB
    const int smem2 = (16384 + 8448 + 512 + 384) * 4;          // ~102.9 KB

    cudaFuncSetAttribute(k0_gemm,    cudaFuncAttributeMaxDynamicSharedMemorySize, smem0);
    cudaFuncSetAttribute(k1_branch1, cudaFuncAttributeMaxDynamicSharedMemorySize, smem1);
    cudaFuncSetAttribute(k2_branch2, cudaFuncAttributeMaxDynamicSharedMemorySize, smem2);

    k0_gemm   <<<256, 256, smem0>>>(X, W1);
    k2_branch2<<<128, 512, smem2>>>(XYZ, Wxyz, bn_g, bn_b);
    k1_branch1<<<128, 1024, smem1>>>(X, XYZ, b1, ln_g, ln_b, out);
}

// round 10
// speedup vs baseline: 1.0898x; 1.0560x over previous
#include <cuda_runtime.h>
#include <cuda_bf16.h>
#include <math.h>

// Problem constants
#define CLOUDS 64
#define PPC    128      // points per cloud
#define DIM    128
#define NNODES (CLOUDS * PPC)   // 8192
#define EPSV   1e-5f

typedef unsigned long long ull;

// ---------------- scratch (device globals; no allocation allowed) -------------
__device__ float g_Ya[NNODES * DIM];    // X @ W1 (k-half 0)
__device__ float g_Yb[NNODES * DIM];    // X @ W1 (k-half 1)
__device__ float g_P2[NNODES * DIM];    // branch-2 pooled
__device__ float g_ps[128 * 128];       // per-CTA partial sums (batchnorm)
__device__ float g_pss[128 * 128];      // per-CTA partial sums of squares
__device__ float g_bstats[256];         // [0:128) scale, [128:256) shift
__device__ unsigned g_cnt;              // last-block ticket (reset each launch)

// ---------------- f32x2 / approx helpers --------------------------------------
__device__ __forceinline__ ull pack2(float lo, float hi) {
    ull r; asm("mov.b64 %0, {%1, %2};" : "=l"(r) : "f"(lo), "f"(hi)); return r;
}
__device__ __forceinline__ void unpack2(ull v, float& lo, float& hi) {
    asm("mov.b64 {%0, %1}, %2;" : "=f"(lo), "=f"(hi) : "l"(v));
}
__device__ __forceinline__ ull fma2(ull a, ull b, ull c) {
    ull d; asm("fma.rn.f32x2 %0, %1, %2, %3;" : "=l"(d) : "l"(a), "l"(b), "l"(c)); return d;
}
__device__ __forceinline__ ull add2(ull a, ull b) {
    ull d; asm("add.rn.f32x2 %0, %1, %2;" : "=l"(d) : "l"(a), "l"(b)); return d;
}
__device__ __forceinline__ float rsqrt_ap(float x) {
    float r; asm("rsqrt.approx.f32 %0, %1;" : "=f"(r) : "f"(x)); return r;
}
__device__ __forceinline__ float ex2_ap(float x) {
    float r; asm("ex2.approx.f32 %0, %1;" : "=f"(r) : "f"(x)); return r;
}

#define NEG1_2 0xBF800000BF800000ULL  // (-1.0f, -1.0f)
#define LOG2E  1.4426950408889634f

// ============================================================================
// K0: Y = X @ W1, K-SPLIT: grid 256 = 128 row-blocks x 2 k-halves.
// ============================================================================
__global__ void __launch_bounds__(256, 2)
k0_gemm(const float* __restrict__ X, const float* __restrict__ W1) {
    extern __shared__ ull sm0[];
    ull* wp = sm0;            // [64 k][64 col-pairs]  (32 KB)
    ull* xd = sm0 + 4096;     // [64 k][64 rows] duplicated (v,v)  (32 KB)

    const int tid = threadIdx.x;
    const int r0  = (blockIdx.x >> 1) * 64;
    const int kb  = (blockIdx.x & 1) * 64;

    const float4* w4 = (const float4*)W1 + kb * 32;
    float4* wps = (float4*)wp;
    #pragma unroll
    for (int t = 0; t < 8; t++) wps[tid + t * 256] = w4[tid + t * 256];

    #pragma unroll
    for (int t = 0; t < 16; t++) {
        int idx = tid + t * 256;      // 0..4095
        int r = idx & 63;
        int k = idx >> 6;
        float v = X[(r0 + r) * DIM + kb + k];
        xd[k * 64 + r] = pack2(v, v);
    }
    __syncthreads();

    const int rb = tid >> 5;
    const int cb = tid & 31;

    ull acc[8][2];
    #pragma unroll
    for (int r = 0; r < 8; r++) { acc[r][0] = 0ULL; acc[r][1] = 0ULL; }

    #pragma unroll 2
    for (int k = 0; k < 64; k++) {
        const ulonglong2* xv = (const ulonglong2*)(xd + k * 64 + rb * 8);
        ulonglong2 x0 = xv[0], x1 = xv[1], x2 = xv[2], x3 = xv[3];
        ull xr[8] = {x0.x, x0.y, x1.x, x1.y, x2.x, x2.y, x3.x, x3.y};
        ulonglong2 wv = *(const ulonglong2*)(wp + k * 64 + cb * 2);
        #pragma unroll
        for (int r = 0; r < 8; r++) {
            acc[r][0] = fma2(xr[r], wv.x, acc[r][0]);
            acc[r][1] = fma2(xr[r], wv.y, acc[r][1]);
        }
    }

    float* dst = (blockIdx.x & 1) ? g_Yb : g_Ya;
    #pragma unroll
    for (int r = 0; r < 8; r++) {
        int row = r0 + rb * 8 + r;
        float a, b, c, d;
        unpack2(acc[r][0], a, b);
        unpack2(acc[r][1], c, d);
        float4 o; o.x = a; o.y = b; o.z = c; o.w = d;
        ((float4*)(dst + row * DIM))[cb] = o;
    }
}

// ============================================================================
// K2: branch 2 (unchanged).  Writes g_P2 + BN partials; last CTA -> g_bstats.
// ============================================================================
#define ST_STRIDE 132
__global__ void __launch_bounds__(512, 1)
k2_branch2(const float* __restrict__ XYZ, const float* __restrict__ Wxyz,
           const float* __restrict__ bn_g, const float* __restrict__ bn_b) {
    extern __shared__ float sm2[];
    float* zs   = sm2;                       // [128][128]       (16384 f)
    float* st   = sm2 + 16384;               // [64][132] stage  (8448 f)
    float* xyzs = sm2 + 16384 + 8448;        // [128][4]         (512 f)
    float* wxs  = xyzs + 512;                // [3][128]         (384 f)

    const int tid  = threadIdx.x;
    const int w    = tid >> 5;
    const int lane = tid & 31;
    const int i_l   = ((w & 1) << 5) | lane;
    const int dbase = (w >> 1) << 4;

    const int cta   = blockIdx.x;
    const int node0 = (cta >> 1) << 7;
    const int i0    = (cta & 1) << 6;

    if (tid < 128) {
        const float* p = XYZ + (node0 + tid) * 3;
        xyzs[tid * 4 + 0] = p[0];
        xyzs[tid * 4 + 1] = p[1];
        xyzs[tid * 4 + 2] = p[2];
        xyzs[tid * 4 + 3] = 0.f;
    }
    if (tid < 384) wxs[tid] = Wxyz[tid];
    __syncthreads();

    #pragma unroll
    for (int t = 0; t < 32; t++) {
        int idx = tid + t * 512;
        int jn = idx >> 7;
        int d  = idx & 127;
        zs[idx] = xyzs[(jn << 2) + 0] * wxs[d]
                + xyzs[(jn << 2) + 1] * wxs[128 + d]
                + xyzs[(jn << 2) + 2] * wxs[256 + d];
    }
    __syncthreads();

    ull zi[8];
    {
        const ull* zsu = (const ull*)zs;
        int zoff = (((i0 + i_l) << 7) + dbase) >> 1;
        #pragma unroll
        for (int p = 0; p < 8; p++) zi[p] = zsu[zoff + p];
    }
    ull acc[8];
    #pragma unroll
    for (int p = 0; p < 8; p++) acc[p] = 0ULL;

    #pragma unroll 4
    for (int j = 0; j < 128; j++) {
        const ulonglong2* zj2 = (const ulonglong2*)(zs + (j << 7) + dbase);
        ulonglong2 a0 = zj2[0], a1 = zj2[1], a2 = zj2[2], a3 = zj2[3];
        ull zj[8] = {a0.x, a0.y, a1.x, a1.y, a2.x, a2.y, a3.x, a3.y};
        #pragma unroll
        for (int p = 0; p < 8; p++) {
            ull df = fma2(zj[p], NEG1_2, zi[p]);      // z_i - z_j
            float lo, hi;
            unpack2(df, lo, hi);
            lo = fmaxf(lo, 0.f);
            hi = fmaxf(hi, 0.f);
            acc[p] = add2(acc[p], pack2(lo, hi));
        }
    }

    float af[16];
    #pragma unroll
    for (int p = 0; p < 8; p++) unpack2(acc[p], af[2 * p], af[2 * p + 1]);
    #pragma unroll
    for (int q = 0; q < 4; q++) {
        float4 o;
        o.x = af[q * 4 + 0]; o.y = af[q * 4 + 1];
        o.z = af[q * 4 + 2]; o.w = af[q * 4 + 3];
        *(float4*)(st + i_l * ST_STRIDE + dbase + q * 4) = o;
    }
    __syncthreads();

    if (tid < 128) {
        float S = 0.f, SS = 0.f;
        #pragma unroll 8
        for (int i = 0; i < 64; i++) {
            float v = st[i * ST_STRIDE + tid];
            S += v; SS += v * v;
        }
        g_ps[cta * 128 + tid]  = S;
        g_pss[cta * 128 + tid] = SS;
    }
    const int nb = node0 + i0;
    #pragma unroll
    for (int t = 0; t < 16; t++) {
        int idx = tid + t * 512;     // 0 .. 8191
        int i = idx >> 7;
        int d = idx & 127;
        g_P2[((nb + i) << 7) + d] = st[i * ST_STRIDE + d];
    }

    // ---- last-block: reduce partials -> g_bstats (deterministic fixed order) ----
    __shared__ unsigned s_tk;
    __threadfence();
    if (tid == 0) s_tk = atomicAdd(&g_cnt, 1u);
    __syncthreads();
    if (s_tk == 127u) {
        __threadfence();
        const int d   = tid & 127;
        const int grp = tid >> 7;       // 0..3, 32 CTAs each
        const float* ps  = g_ps  + grp * 32 * 128 + d;
        const float* pss = g_pss + grp * 32 * 128 + d;
        float S = 0.f, SS = 0.f;
        #pragma unroll 8
        for (int c = 0; c < 32; c++) {
            S  += ps[c * 128];
            SS += pss[c * 128];
        }
        st[grp * 128 + d]       = S;     // reuse st
        st[512 + grp * 128 + d] = SS;
        __syncthreads();
        if (tid < 128) {
            float St  = st[tid] + st[128 + tid] + st[256 + tid] + st[384 + tid];
            float SSt = st[512 + tid] + st[640 + tid] + st[768 + tid] + st[896 + tid];
            float mu  = St * (1.f / (float)NNODES);
            float var = SSt * (1.f / (float)NNODES) - mu * mu;
            float inv = 1.f / sqrtf(var + EPSV);
            float scale = inv * bn_g[tid];
            g_bstats[tid]       = scale;
            g_bstats[128 + tid] = bn_b[tid] - mu * scale;
        }
        __threadfence();
        if (tid == 0) g_cnt = 0u;       // reset for next launch
    }
}

// ============================================================================
// K1: branch 1 + fused output.  NEW MAPPING: 1024 threads = 32 warps;
// warp = i-pair (iA = 2w, iB = 2w+1 local), lane = d-chunk of 4 floats.
//   - yj load: ONE distinct coalesced LDS.128/warp/j (whole 512B y_j row)
//   - w load: ONE broadcast LDS.64/warp/j (both w values)
//   - LayerNorm reduction: pure warp shuffles (no smem, no barriers)
//   out = x + LN(p1)*ln_g + ln_b + p2*bn_scale + bn_shift
// ============================================================================
__global__ void __launch_bounds__(1024, 1)
k1_branch1(const float* __restrict__ X, const float* __restrict__ XYZ,
           const float* __restrict__ b1, const float* __restrict__ ln_g,
           const float* __restrict__ ln_b, float* __restrict__ out) {
    extern __shared__ float sm1[];
    float* ys   = sm1;            // [128][128] Y of the cloud     (16384 f)
    float* ws   = sm1 + 16384;    // [128 j][64 i] edge weights     (8192 f)
    float* xyzs = sm1 + 24576;    // [128][4] xyz of the cloud      (512 f)

    const int tid  = threadIdx.x;
    const int w    = tid >> 5;        // 0..31  (i-pair index)
    const int lane = tid & 31;        // d-chunk
    const int iA   = w << 1;          // local i, even
    const int iB   = iA + 1;          // local i, odd
    const int dbase = lane << 2;      // 0..124 step 4

    const int cta   = blockIdx.x;
    const int node0 = (cta >> 1) << 7;   // cloud * 128
    const int i0    = (cta & 1) << 6;    // 0 or 64

    // load cloud Y = g_Ya + g_Yb
    {
        const float4* Ya = (const float4*)(g_Ya + node0 * DIM);
        const float4* Yb = (const float4*)(g_Yb + node0 * DIM);
        float4* ysv = (float4*)ys;
        #pragma unroll
        for (int t = 0; t < 4; t++) {
            int idx = tid + t * 1024;
            float4 a = Ya[idx], b = Yb[idx];
            float4 o; o.x = a.x + b.x; o.y = a.y + b.y; o.z = a.z + b.z; o.w = a.w + b.w;
            ysv[idx] = o;
        }
    }
    if (tid < 128) {
        const float* p = XYZ + (node0 + tid) * 3;
        xyzs[tid * 4 + 0] = p[0];
        xyzs[tid * 4 + 1] = p[1];
        xyzs[tid * 4 + 2] = p[2];
        xyzs[tid * 4 + 3] = 0.f;
    }
    __syncthreads();

    // precompute w matrix: ws[j*64 + i] = exp(-dist(i0+i, j)); diag -> w=1
    #pragma unroll
    for (int t = 0; t < 8; t++) {
        int idx = tid + t * 1024;
        int ii = idx & 63;
        int jj = idx >> 6;
        float dx = xyzs[((i0 + ii) << 2) + 0] - xyzs[(jj << 2) + 0];
        float dy = xyzs[((i0 + ii) << 2) + 1] - xyzs[(jj << 2) + 1];
        float dz = xyzs[((i0 + ii) << 2) + 2] - xyzs[(jj << 2) + 2];
        float d2 = dx * dx + dy * dy + dz * dz;
        float dist = d2 * rsqrt_ap(fmaxf(d2, 1e-30f));   // sqrt(d2)
        ws[(jj << 6) + ii] = ex2_ap(-dist * LOG2E);      // exp(-dist)
    }

    // cache y_i (two rows) and b1 as packed pairs (2 ull = 4 floats each)
    ull yiA[2], yiB[2], b1p[2];
    {
        const ull* b1u = (const ull*)b1;
        b1p[0] = b1u[lane * 2 + 0];
        b1p[1] = b1u[lane * 2 + 1];
    }
    __syncthreads();      // ws ready; ys ready
    {
        const ull* ysu = (const ull*)ys;
        int offA = (i0 + iA) * 64 + lane * 2;
        int offB = (i0 + iB) * 64 + lane * 2;
        yiA[0] = ysu[offA]; yiA[1] = ysu[offA + 1];
        yiB[0] = ysu[offB]; yiB[1] = ysu[offB + 1];
    }
    ull accA[2] = {0ULL, 0ULL}, accB[2] = {0ULL, 0ULL};

    // ---- main pairwise loop over j ----
    #pragma unroll 4
    for (int j = 0; j < 128; j++) {
        // both edge weights for this warp's i-pair: one broadcast LDS.64
        ull wv = *(const ull*)(ws + (j << 6) + iA);
        float w0, w1;
        unpack2(wv, w0, w1);
        ull w20 = pack2(w0, w0);
        ull w21 = pack2(w1, w1);
        // whole y_j row via distinct coalesced LDS.128 (lane -> d-chunk)
        ulonglong2 yj = *(const ulonglong2*)(ys + (j << 7) + dbase);
        ull yjp[2] = {yj.x, yj.y};
        #pragma unroll
        for (int p = 0; p < 2; p++) {
            ull dfA = fma2(yjp[p], NEG1_2, yiA[p]);
            ull tA  = fma2(w20, dfA, b1p[p]);
            float lo, hi;
            unpack2(tA, lo, hi);
            lo = fmaxf(lo, 0.f); hi = fmaxf(hi, 0.f);
            accA[p] = add2(accA[p], pack2(lo, hi));

            ull dfB = fma2(yjp[p], NEG1_2, yiB[p]);
            ull tB  = fma2(w21, dfB, b1p[p]);
            unpack2(tB, lo, hi);
            lo = fmaxf(lo, 0.f); hi = fmaxf(hi, 0.f);
            accB[p] = add2(accB[p], pack2(lo, hi));
        }
    }

    // ---- epilogue: self-edge correction + warp-shuffle LayerNorm + fused BN ----
    float afA[4], afB[4];
    #pragma unroll
    for (int p = 0; p < 2; p++) {
        float bl, bh; unpack2(b1p[p], bl, bh);
        float rb0 = fmaxf(bl, 0.f), rb1 = fmaxf(bh, 0.f);
        float lo, hi;
        unpack2(accA[p], lo, hi);
        afA[2 * p + 0] = lo - rb0;
        afA[2 * p + 1] = hi - rb1;
        unpack2(accB[p], lo, hi);
        afB[2 * p + 0] = lo - rb0;
        afB[2 * p + 1] = hi - rb1;
    }
    float sA = 0.f, qA = 0.f, sB = 0.f, qB = 0.f;
    #pragma unroll
    for (int k = 0; k < 4; k++) {
        sA += afA[k]; qA += afA[k] * afA[k];
        sB += afB[k]; qB += afB[k] * afB[k];
    }
    #pragma unroll
    for (int off = 16; off > 0; off >>= 1) {
        sA += __shfl_xor_sync(0xffffffffu, sA, off);
        qA += __shfl_xor_sync(0xffffffffu, qA, off);
        sB += __shfl_xor_sync(0xffffffffu, sB, off);
        qB += __shfl_xor_sync(0xffffffffu, qB, off);
    }
    float muA  = sA * (1.f / 128.f);
    float invA = 1.f / sqrtf(qA * (1.f / 128.f) - muA * muA + EPSV);
    float muB  = sB * (1.f / 128.f);
    float invB = 1.f / sqrtf(qB * (1.f / 128.f) - muB * muB + EPSV);

    float4 gv = *(const float4*)(ln_g + dbase);
    float4 bv = *(const float4*)(ln_b + dbase);
    float4 sc = *(const float4*)(g_bstats + dbase);
    float4 sh = *(const float4*)(g_bstats + 128 + dbase);

    int gbA = ((node0 + i0 + iA) << 7) + dbase;
    int gbB = ((node0 + i0 + iB) << 7) + dbase;
    {
        float4 xv = *(const float4*)(X + gbA);
        float4 pv = *(const float4*)(g_P2 + gbA);
        float4 o;
        o.x = xv.x + (afA[0] - muA) * invA * gv.x + bv.x + pv.x * sc.x + sh.x;
        o.y = xv.y + (afA[1] - muA) * invA * gv.y + bv.y + pv.y * sc.y + sh.y;
        o.z = xv.z + (afA[2] - muA) * invA * gv.z + bv.z + pv.z * sc.z + sh.z;
        o.w = xv.w + (afA[3] - muA) * invA * gv.w + bv.w + pv.w * sc.w + sh.w;
        *(float4*)(out + gbA) = o;
    }
    {
        float4 xv = *(const float4*)(X + gbB);
        float4 pv = *(const float4*)(g_P2 + gbB);
        float4 o;
        o.x = xv.x + (afB[0] - muB) * invB * gv.x + bv.x + pv.x * sc.x + sh.x;
        o.y = xv.y + (afB[1] - muB) * invB * gv.y + bv.y + pv.y * sc.y + sh.y;
        o.z = xv.z + (afB[2] - muB) * invB * gv.z + bv.z + pv.z * sc.z + sh.z;
        o.w = xv.w + (afB[3] - muB) * invB * gv.w + bv.w + pv.w * sc.w + sh.w;
        *(float4*)(out + gbB) = o;
    }
}

// ============================================================================
extern "C" void kernel_launch(void* const* d_in, const int* in_sizes, int n_in,
                              void* d_out, int out_size) {
    const float* X    = (const float*)d_in[0];
    const float* XYZ  = (const float*)d_in[1];
    const float* Wxyz = (const float*)d_in[2];
    const float* bn_g = (const float*)d_in[3];
    const float* bn_b = (const float*)d_in[4];
    const float* W1   = (const float*)d_in[5];
    const float* b1   = (const float*)d_in[6];
    const float* ln_g = (const float*)d_in[7];
    const float* ln_b = (const float*)d_in[8];
    float* out = (float*)d_out;

    const int smem0 = 8192 * 8;                                // 64 KB
    const int smem1 = (16384 + 8192 + 512) * 4;                // ~100.4 KB
    const int smem2 = (16384 + 8448 + 512 + 384) * 4;          // ~102.9 KB

    cudaFuncSetAttribute(k0_gemm,    cudaFuncAttributeMaxDynamicSharedMemorySize, smem0);
    cudaFuncSetAttribute(k1_branch1, cudaFuncAttributeMaxDynamicSharedMemorySize, smem1);
    cudaFuncSetAttribute(k2_branch2, cudaFuncAttributeMaxDynamicSharedMemorySize, smem2);

    // Fork-join: k0 (legacy stream) runs concurrently with k2 (forked stream).
    // Stream/events are intentionally NOT destroyed here: destroying a stream
    // that participates in an in-progress capture invalidates the capture.
    // A handful of host-side handles leak across the harness's few eager calls.
    cudaStream_t s1;
    cudaStreamCreateWithFlags(&s1, cudaStreamNonBlocking);
    cudaEvent_t evA, evB;
    cudaEventCreateWithFlags(&evA, cudaEventDisableTiming);
    cudaEventCreateWithFlags(&evB, cudaEventDisableTiming);

    cudaEventRecord(evA, 0);
    cudaStreamWaitEvent(s1, evA, 0);

    k0_gemm   <<<256, 256, smem0>>>(X, W1);                    // legacy stream
    k2_branch2<<<128, 512, smem2, s1>>>(XYZ, Wxyz, bn_g, bn_b); // forked stream

    cudaEventRecord(evB, s1);
    cudaStreamWaitEvent(0, evB, 0);

    k1_branch1<<<128, 1024, smem1>>>(X, XYZ, b1, ln_g, ln_b, out);
}